// round 15
// baseline (speedup 1.0000x reference)
#include <cuda_runtime.h>

#define NLVL   16
#define WIDTH  1000
#define PADW   (WIDTH + 4)     // w in [-2, 1001]
#define TPB    1024

typedef unsigned long long u64;
typedef unsigned int       u32;

// ---------------- packed f32x2 helpers ----------------
__device__ __forceinline__ u64 pk(float lo, float hi) {
    u64 r; asm("mov.b64 %0, {%1,%2};" : "=l"(r) : "f"(lo), "f"(hi)); return r;
}
__device__ __forceinline__ void upk(float& lo, float& hi, u64 v) {
    asm("mov.b64 {%0,%1}, %2;" : "=f"(lo), "=f"(hi) : "l"(v));
}
__device__ __forceinline__ u64 f2fma(u64 a, u64 b, u64 c) {
    u64 r; asm("fma.rn.f32x2 %0, %1, %2, %3;" : "=l"(r) : "l"(a), "l"(b), "l"(c)); return r;
}
__device__ __forceinline__ u64 f2add(u64 a, u64 b) {
    u64 r; asm("add.rn.f32x2 %0, %1, %2;" : "=l"(r) : "l"(a), "l"(b)); return r;
}
__device__ __forceinline__ u64 f2sub(u64 a, u64 b) {
    u64 r; asm("sub.rn.f32x2 %0, %1, %2;" : "=l"(r) : "l"(a), "l"(b)); return r;
}
__device__ __forceinline__ u64 f2mul(u64 a, u64 b) {
    u64 r; asm("mul.rn.f32x2 %0, %1, %2;" : "=l"(r) : "l"(a), "l"(b)); return r;
}

__device__ __forceinline__ float hwsin(float r) {   // r in [-pi, pi]
    float s; asm("sin.approx.f32 %0, %1;" : "=f"(s) : "f"(r)); return s;
}

__device__ __forceinline__ u64 lds64(u32 addr, int imm_off) {
    u64 v;
    asm("ld.shared.b64 %0, [%1];" : "=l"(v) : "r"(addr + (u32)imm_off));
    return v;
}

__global__ __launch_bounds__(TPB, 1)
void trig_hash_kernel(const float* __restrict__ x,
                      const float* __restrict__ grids,
                      const float* __restrict__ G,
                      const float* __restrict__ H,
                      float2* __restrict__ out,
                      int n_duos)      // B*8 : thread-iteration = (sample, level-duo)
{
    extern __shared__ float2 gsm[];    // [(w+2)*16 + n]

    // Stage grids (N,C,W) -> transposed padded smem. Zeros outside [0,W).
    for (int j = threadIdx.x; j < PADW * NLVL; j += TPB) {
        int n = j & (NLVL - 1);
        int w = (j >> 4) - 2;
        float c0 = 0.f, c1 = 0.f;
        if ((unsigned)w < (unsigned)WIDTH) {
            c0 = grids[(n * 2 + 0) * WIDTH + w];
            c1 = grids[(n * 2 + 1) * WIDTH + w];
        }
        gsm[j] = make_float2(c0, c1);
    }
    __syncthreads();

    const int gtid   = blockIdx.x * TPB + threadIdx.x;
    const int stride = gridDim.x * TPB;       // multiple of 8
    const int m      = gtid & 7;              // level duo: levels 2m, 2m+1
    const int o      = (threadIdx.x >> 3) & 1; // octet swap bit (conflict breaker)

    // Octet-swapped level assignment: item0 = level n0, item1 = level n1.
    // Load-instruction addresses mod 128 = 16m + 8o -> 16 distinct per phase.
    const int n0 = 2 * m + o;
    const int n1 = 2 * m + 1 - o;

    // Per-duo constants, TURNS-scaled, packed (n0 in lo, n1 in hi).
    const float S = 0.15915494309189535f;
    const u64 G00 = pk(G[  0+n0]*S, G[  0+n1]*S), G01 = pk(G[ 16+n0]*S, G[ 16+n1]*S),
              G02 = pk(G[ 32+n0]*S, G[ 32+n1]*S);
    const u64 G10 = pk(G[ 48+n0]*S, G[ 48+n1]*S), G11 = pk(G[ 64+n0]*S, G[ 64+n1]*S),
              G12 = pk(G[ 80+n0]*S, G[ 80+n1]*S);
    const u64 G20 = pk(G[ 96+n0]*S, G[ 96+n1]*S), G21 = pk(G[112+n0]*S, G[112+n1]*S),
              G22 = pk(G[128+n0]*S, G[128+n1]*S);
    const u64 H0  = pk(H[  0+n0]*S, H[  0+n1]*S), H1  = pk(H[ 16+n0]*S, H[ 16+n1]*S),
              H2  = pk(H[ 32+n0]*S, H[ 32+n1]*S);

    const u64 MAGIC = pk(12582912.0f, 12582912.0f);      // 1.5 * 2^23
    const u64 TWOPI = pk(6.2831853071795865f, 6.2831853071795865f);
    const u64 ONEp  = pk(1.0f, 1.0f);
    const u64 C075p = pk(0.75f, 0.75f);
    const u64 C125p = pk(1.25f, 1.25f);
    const float MAG499 = 12583411.0f;                    // 12582912 + 499, exact

    u32 smbase;
    asm("{ .reg .u64 t; cvta.to.shared.u64 t, %1; cvt.u32.u64 %0, t; }"
        : "=r"(smbase) : "l"(gsm));
    // level n tap0 addr = bits(bb_n)*128 + (smbase + 128 + 8n - 0xA0000000)
    const u32 addrc0 = smbase + 128u + (u32)(8 * n0) - 0xA0000000u;
    const u32 addrc1 = smbase + 128u + (u32)(8 * n1) - 0xA0000000u;

    // ---- preload x for the first iteration (one sample = 3 scalars) ----
    float q0, q1, q2;
    {
        const float* xp = x + 3 * (((gtid < n_duos) ? gtid : 0) >> 3);
        q0 = xp[0]; q1 = xp[1]; q2 = xp[2];
    }

    for (int p = gtid; p < n_duos; p += stride) {
        // ---- prefetch next iteration's x ----
        int pn = p + stride;
        const float* xn = x + 3 * ((((pn < n_duos) ? pn : p)) >> 3);
        float f0 = xn[0], f1 = xn[1], f2v = xn[2];

        // ---- broadcast-sample packed a-chain (turns) : lo=n0, hi=n1 ----
        u64 X0 = pk(q0, q0);
        u64 X1 = pk(q1, q1);
        u64 X2 = pk(q2, q2);
        u64 a0 = f2fma(X0, G00, f2fma(X1, G10, f2fma(X2, G20, H0)));
        u64 a1 = f2fma(X0, G01, f2fma(X1, G11, f2fma(X2, G21, H1)));
        u64 a2 = f2fma(X0, G02, f2fma(X1, G12, f2fma(X2, G22, H2)));

        // turns reduction: rt = a - rint(a) (exact), then *2pi
        u64 kb0 = f2add(a0, MAGIC), kb1 = f2add(a1, MAGIC), kb2 = f2add(a2, MAGIC);
        u64 rr0 = f2mul(f2sub(a0, f2sub(kb0, MAGIC)), TWOPI);
        u64 rr1 = f2mul(f2sub(a1, f2sub(kb1, MAGIC)), TWOPI);
        u64 rr2 = f2mul(f2sub(a2, f2sub(kb2, MAGIC)), TWOPI);
        float r0A, r0B, r1A, r1B, r2A, r2B;
        upk(r0A, r0B, rr0); upk(r1A, r1B, rr1); upk(r2A, r2B, rr2);

        float gxA = hwsin(r0A) * hwsin(r1A) * hwsin(r2A);   // level n0
        float gxB = hwsin(r0B) * hwsin(r1B) * hwsin(r2B);   // level n1

        // fused ix chain: ix = 500*gx + 499.5
        float bbA = fmaf(gxA, 500.0f, MAG499);        // MAGIC + floor(ix)
        float bbB = fmaf(gxB, 500.0f, MAG499);
        float xfA = bbA - 12582912.0f;
        float xfB = bbB - 12582912.0f;
        float tA  = fmaf(gxA, 500.0f, 499.5f - xfA);  // t = ix - base
        float tB  = fmaf(gxB, 500.0f, 499.5f - xfB);

        // ---- 8 channel-packed tap loads (conflict-free: mod-128 slots distinct) ----
        const u32 adA = __float_as_uint(bbA) * 128u + addrc0;   // level n0
        const u32 adB = __float_as_uint(bbB) * 128u + addrc1;   // level n1
        u64 vA0 = lds64(adA,   0), vA1 = lds64(adA, 128);
        u64 vA2 = lds64(adA, 256), vA3 = lds64(adA, 384);
        u64 vB0 = lds64(adB,   0), vB1 = lds64(adB, 128);
        u64 vB2 = lds64(adB, 256), vB3 = lds64(adB, 384);

        // ---- packed cubic weights (n0 in lo, n1 in hi), u = t^2 - t ----
        u64 tp  = pk(tA, tB);
        u64 tm1 = f2sub(tp, ONEp);
        u64 u   = f2mul(tp, tm1);
        u64 v   = f2mul(C075p, u);
        u64 W3  = f2mul(v, tp);
        u64 W0  = f2sub(v, W3);
        u64 omt = f2sub(ONEp, tp);
        u64 z   = f2mul(u, tp);
        u64 h   = f2sub(omt, u);
        u64 W1  = f2fma(C125p, z, h);
        u64 r_  = f2sub(ONEp, W0);
        r_      = f2sub(r_, W1);
        u64 W2  = f2sub(r_, W3);

        float w0A,w0B,w1A,w1B,w2A,w2B,w3A,w3B;
        upk(w0A, w0B, W0); upk(w1A, w1B, W1);
        upk(w2A, w2B, W2); upk(w3A, w3B, W3);

        // ---- channel-packed accumulation ----
        u64 accA = f2mul(vA3, pk(w3A, w3A));          // level n0
        accA = f2fma(vA2, pk(w2A, w2A), accA);
        accA = f2fma(vA1, pk(w1A, w1A), accA);
        accA = f2fma(vA0, pk(w0A, w0A), accA);
        u64 accB = f2mul(vB3, pk(w3B, w3B));          // level n1
        accB = f2fma(vB2, pk(w2B, w2B), accB);
        accB = f2fma(vB1, pk(w1B, w1B), accB);
        accB = f2fma(vB0, pk(w0B, w0B), accB);

        // outputs adjacent: float2 idx s*16+2m = 2p (level 2m), 2p+1 (level 2m+1)
        // o=0: (accA, accB) ; o=1: (accB, accA)
        ulonglong2 ov;
        ov.x = o ? accB : accA;
        ov.y = o ? accA : accB;
        ((ulonglong2*)out)[p] = ov;

        // rotate x
        q0 = f0; q1 = f1; q2 = f2v;
    }
}

extern "C" void kernel_launch(void* const* d_in, const int* in_sizes, int n_in,
                              void* d_out, int out_size)
{
    const float* x     = (const float*)d_in[0];
    const float* grids = (const float*)d_in[1];
    const float* G     = (const float*)d_in[2];
    const float* H     = (const float*)d_in[3];
    (void)n_in; (void)out_size;

    const int B      = in_sizes[0] / 3;
    const int n_duos = B * 8;            // (sample, level-duo) work items

    const int smem_bytes = PADW * NLVL * (int)sizeof(float2);   // 128512

    cudaFuncSetAttribute(trig_hash_kernel,
                         cudaFuncAttributeMaxDynamicSharedMemorySize, smem_bytes);

    int sm_count = 148;
    cudaDeviceGetAttribute(&sm_count, cudaDevAttrMultiProcessorCount, 0);

    trig_hash_kernel<<<sm_count, TPB, smem_bytes>>>(
        x, grids, G, H, (float2*)d_out, n_duos);
}